// round 3
// baseline (speedup 1.0000x reference)
#include <cuda_runtime.h>
#include <math.h>

// Fixed problem shapes (from reference setup_inputs):
// b=8, n=4096, c=32, g=4, rad=4, rank=2, k=128, in=1024, OUT=1024
#define BB    8
#define CC    32
#define GG    4
#define RADR  4
#define KK    128
#define PPC   12          // 4 neighbor + 4 sampled + 4 range-restricted
#define NP    384         // CC * PPC points per (b,k) tile
#define INSZ  1024
#define OUTSZ 1024
#define NWARP 12          // NP/32

__global__ __launch_bounds__(NP) void sparse_layer_kernel(
    const float* __restrict__ x,        // (8, 1024)
    const float* __restrict__ means,    // (8, 4096, 2)
    const float* __restrict__ sigmas,   // (8, 4096, 2)
    const float* __restrict__ values,   // (8, 4096)
    const float* __restrict__ su,       // (8, 128, 32, 4, 2)
    const float* __restrict__ ru,       // (8, 128, 32, 4, 2)
    float* __restrict__ out)            // (8, 1024)
{
    __shared__ float sm0[CC], sm1[CC], si0[CC], si1[CC], sval[CC];
    __shared__ int   sids[NP];              // bit31 = dup flag, low 20 bits = i0*1024+i1
    __shared__ float spart[NWARP * CC];
    __shared__ float svalw[CC];

    const int bk = blockIdx.x;              // b*128 + k
    const int b  = bk >> 7;
    const int t  = threadIdx.x;
    const int w  = t >> 5;
    const int l  = t & 31;

    // ---- load per-cell params ----
    if (t < CC) {
        int base = (bk * CC + t) * 2;
        sm0[t] = means[base];
        sm1[t] = means[base + 1];
        si0[t] = sqrtf(1.0f / (1e-6f + sigmas[base]));
        si1[t] = sqrtf(1.0f / (1e-6f + sigmas[base + 1]));
        sval[t] = values[bk * CC + t];
    }
    __syncthreads();

    // ---- generate integer tuple for this thread's point: cell c = t/12, slot j ----
    {
        const int c = t / PPC;
        const int j = t - c * PPC;
        const float m0v = sm0[c], m1v = sm1[c];
        const float SCL = 1.0f - 1e-6f;
        int i0, i1;
        if (j < 4) {
            // fm order from itertools.product([T,F],rank=2): True -> floor
            // j=0:(fl,fl) j=1:(fl,ce) j=2:(ce,fl) j=3:(ce,ce)
            i0 = (j & 2) ? (int)ceilf(m0v) : (int)floorf(m0v);
            i1 = (j & 1) ? (int)ceilf(m1v) : (int)floorf(m1v);
        } else if (j < 8) {
            int idx = ((bk * CC + c) * GG + (j - 4)) * 2;
            i0 = (int)floorf(__fmul_rn(__fmul_rn(su[idx],     SCL), 1024.0f));
            i1 = (int)floorf(__fmul_rn(__fmul_rn(su[idx + 1], SCL), 1024.0f));
        } else {
            int idx = ((bk * CC + c) * RADR + (j - 8)) * 2;
            float mn0 = rintf(m0v), mn1 = rintf(m1v);   // round half-to-even (matches jnp.round)
            float lo0 = mn0 - 8.0f, lo1 = mn1 - 8.0f;
            if (lo0 < 0.0f) lo0 = 0.0f;
            if (mn0 + 8.0f > 1024.0f) lo0 = 1008.0f;
            if (lo1 < 0.0f) lo1 = 0.0f;
            if (mn1 + 8.0f > 1024.0f) lo1 = 1008.0f;
            i0 = (int)floorf(__fadd_rn(__fmul_rn(__fmul_rn(ru[idx],     SCL), 16.0f), lo0));
            i1 = (int)floorf(__fadd_rn(__fmul_rn(__fmul_rn(ru[idx + 1], SCL), 16.0f), lo1));
        }
        sids[t] = (i0 << 10) | i1;
    }
    __syncthreads();

    // ---- duplicate marking: dup iff same id at smaller index (stable-sort semantics) ----
    {
        const int myid = sids[t];
        bool dup = false;
        for (int jj = 0; jj < t; ++jj) {            // broadcast LDS, early exit
            if (sids[jj] == myid) { dup = true; break; }
        }
        __syncthreads();
        if (dup) sids[t] = myid | 0x80000000;
    }
    __syncthreads();

    // ---- density pass: warp w owns points [32w,32w+32), lane = cell c ----
    const float m0 = sm0[l], m1 = sm1[l];
    const float v0 = si0[l], v1 = si1[l];
    float e[32];
    float colp = 0.0f;
    #pragma unroll
    for (int ii = 0; ii < 32; ++ii) {
        int idr = sids[(w << 5) + ii];              // broadcast
        float p0 = (float)((idr >> 10) & 1023);
        float p1 = (float)(idr & 1023);
        float d0 = (p0 - m0) * v0;
        float d1 = (p1 - m1) * v1;
        float s  = d0 * d0 + d1 * d1;
        float ee = (idr < 0) ? 0.0f : __expf(-0.5f * s);
        e[ii] = ee;
        colp += ee;
    }
    spart[w * CC + l] = colp;
    __syncthreads();

    // ---- column sums and value/colsum weights ----
    if (t < CC) {
        float s = 0.0f;
        #pragma unroll
        for (int ww = 0; ww < NWARP; ++ww) s += spart[ww * CC + t];
        svalw[t] = sval[t] / s;
    }
    __syncthreads();

    // ---- weighted sum per point + scatter ----
    const float vw = svalw[l];
    const float* xrow = x + b * INSZ;
    float* orow = out + b * OUTSZ;
    #pragma unroll
    for (int ii = 0; ii < 32; ++ii) {
        float pe = e[ii] * vw;
        pe += __shfl_xor_sync(0xffffffffu, pe, 16);
        pe += __shfl_xor_sync(0xffffffffu, pe, 8);
        pe += __shfl_xor_sync(0xffffffffu, pe, 4);
        pe += __shfl_xor_sync(0xffffffffu, pe, 2);
        pe += __shfl_xor_sync(0xffffffffu, pe, 1);
        if (l == 0) {
            int idr = sids[(w << 5) + ii];
            if (idr >= 0) {                          // dup rows contribute exactly 0
                float contrib = pe * xrow[idr & 1023];
                atomicAdd(&orow[(idr >> 10) & 1023], contrib);
            }
        }
    }
}

extern "C" void kernel_launch(void* const* d_in, const int* in_sizes, int n_in,
                              void* d_out, int out_size)
{
    const float* x      = (const float*)d_in[0];
    const float* means  = (const float*)d_in[1];
    const float* sigmas = (const float*)d_in[2];
    const float* values = (const float*)d_in[3];
    const float* su     = (const float*)d_in[4];
    const float* ru     = (const float*)d_in[5];
    float* out = (float*)d_out;

    cudaMemsetAsync(out, 0, (size_t)out_size * sizeof(float));
    sparse_layer_kernel<<<BB * KK, NP>>>(x, means, sigmas, values, su, ru, out);
}

// round 4
// speedup vs baseline: 2.7664x; 2.7664x over previous
#include <cuda_runtime.h>
#include <math.h>

// Fixed problem shapes: b=8, n=4096, c=32, g=4, rad=4, rank=2, k=128, in=1024, OUT=1024
#define BB    8
#define CC    32
#define GG    4
#define RADR  4
#define KK    128
#define PPC   12          // 4 neighbor + 4 sampled + 4 range-restricted
#define NP    384         // CC * PPC points per (b,k) tile
#define INSZ  1024
#define OUTSZ 1024
#define NWARP 12          // NP/32
#define HSZ   1024        // dup-hash slots (power of 2)

__global__ __launch_bounds__(NP) void sparse_layer_kernel(
    const float* __restrict__ x,        // (8, 1024)
    const float* __restrict__ means,    // (8, 4096, 2)
    const float* __restrict__ sigmas,   // (8, 4096, 2)
    const float* __restrict__ values,   // (8, 4096)
    const float* __restrict__ su,       // (8, 128, 32, 4, 2)
    const float* __restrict__ ru,       // (8, 128, 32, 4, 2)
    float* __restrict__ out)            // (8, 1024)
{
    __shared__ float sm0[CC], sm1[CC], si0[CC], si1[CC], sval[CC];
    __shared__ int   sids[NP];              // bit31 = dup flag, low 20 bits = i0*1024+i1
    __shared__ float spart[NWARP * CC];
    __shared__ float svalw[CC];
    __shared__ unsigned int tab[HSZ];       // hash: (id<<9)|minidx, EMPTY=0xFFFFFFFF

    const int bk = blockIdx.x;              // b*128 + k
    const int b  = bk >> 7;
    const int t  = threadIdx.x;
    const int w  = t >> 5;
    const int l  = t & 31;

    // ---- init hash + load per-cell params ----
    #pragma unroll
    for (int i = t; i < HSZ; i += NP) tab[i] = 0xFFFFFFFFu;
    if (t < CC) {
        int base = (bk * CC + t) * 2;
        sm0[t] = means[base];
        sm1[t] = means[base + 1];
        si0[t] = sqrtf(1.0f / (1e-6f + sigmas[base]));
        si1[t] = sqrtf(1.0f / (1e-6f + sigmas[base + 1]));
        sval[t] = values[bk * CC + t];
    }
    __syncthreads();

    // ---- generate integer tuple for this thread's point: cell c = t/12, slot j ----
    int id;
    {
        const int c = t / PPC;
        const int j = t - c * PPC;
        const float m0v = sm0[c], m1v = sm1[c];
        const float SCL = 1.0f - 1e-6f;
        int i0, i1;
        if (j < 4) {
            // fm order (itertools.product([T,F],2)): True->floor
            i0 = (j & 2) ? (int)ceilf(m0v) : (int)floorf(m0v);
            i1 = (j & 1) ? (int)ceilf(m1v) : (int)floorf(m1v);
        } else if (j < 8) {
            int idx = ((bk * CC + c) * GG + (j - 4)) * 2;
            i0 = (int)floorf(__fmul_rn(__fmul_rn(su[idx],     SCL), 1024.0f));
            i1 = (int)floorf(__fmul_rn(__fmul_rn(su[idx + 1], SCL), 1024.0f));
        } else {
            int idx = ((bk * CC + c) * RADR + (j - 8)) * 2;
            float mn0 = rintf(m0v), mn1 = rintf(m1v);   // round half-even (jnp.round)
            float lo0 = mn0 - 8.0f, lo1 = mn1 - 8.0f;
            if (lo0 < 0.0f) lo0 = 0.0f;
            if (mn0 + 8.0f > 1024.0f) lo0 = 1008.0f;
            if (lo1 < 0.0f) lo1 = 0.0f;
            if (mn1 + 8.0f > 1024.0f) lo1 = 1008.0f;
            i0 = (int)floorf(__fadd_rn(__fmul_rn(__fmul_rn(ru[idx],     SCL), 16.0f), lo0));
            i1 = (int)floorf(__fadd_rn(__fmul_rn(__fmul_rn(ru[idx + 1], SCL), 16.0f), lo1));
        }
        id = (i0 << 10) | i1;
    }

    // ---- duplicate marking via shared hash (first occurrence by thread index wins) ----
    {
        const unsigned int uid = (unsigned int)id;
        const unsigned int val = (uid << 9) | (unsigned int)t;   // 20+9 bits < 2^29
        unsigned int h = (uid * 2654435761u) >> 22;              // top 10 bits
        int slot;
        for (;;) {
            unsigned int old = atomicCAS(&tab[h], 0xFFFFFFFFu, val);
            if (old == 0xFFFFFFFFu) { slot = h; break; }         // claimed slot
            if ((old >> 9) == uid)  { atomicMin(&tab[h], val); slot = h; break; }
            h = (h + 1) & (HSZ - 1);
        }
        __syncthreads();
        bool dup = ((tab[slot] & 511u) != (unsigned int)t);
        sids[t] = dup ? (id | (int)0x80000000) : id;
    }
    __syncthreads();

    // ---- density pass: warp w owns points [32w,32w+32), lane = cell ----
    const float m0 = sm0[l], m1 = sm1[l];
    const float v0 = si0[l], v1 = si1[l];
    float e[32];
    float colp = 0.0f;
    #pragma unroll
    for (int ii = 0; ii < 32; ++ii) {
        int idr = sids[(w << 5) + ii];              // LDS broadcast
        float p0 = (float)((idr >> 10) & 1023);
        float p1 = (float)(idr & 1023);
        float d0 = (p0 - m0) * v0;
        float d1 = (p1 - m1) * v1;
        float s  = d0 * d0 + d1 * d1;
        float ee = (idr < 0) ? 0.0f : __expf(-0.5f * s);
        e[ii] = ee;
        colp += ee;
    }
    spart[w * CC + l] = colp;
    __syncthreads();

    // ---- column sums and value/colsum weights ----
    if (t < CC) {
        float s = 0.0f;
        #pragma unroll
        for (int ww = 0; ww < NWARP; ++ww) s += spart[ww * CC + t];
        svalw[t] = sval[t] / s;
    }
    __syncthreads();

    // ---- per-point weighted sums via 32x32 register transpose-reduce ----
    // Before: e[ii] on lane l = w(point w*32+ii, cell l). After: e[0] on lane l =
    // sum over cells for point w*32+l.
    {
        const float vwl = svalw[l];
        #pragma unroll
        for (int ii = 0; ii < 32; ++ii) e[ii] *= vwl;

        #pragma unroll
        for (int mask = 16; mask >= 1; mask >>= 1) {
            const bool hi = (l & mask) != 0;
            #pragma unroll
            for (int j = 0; j < mask; ++j) {
                float a = e[j], bq = e[j + mask];
                float keep = hi ? bq : a;
                float give = hi ? a : bq;
                e[j] = keep + __shfl_xor_sync(0xffffffffu, give, mask);
            }
        }
    }

    // ---- scatter: one atomic per live point, 32 lanes in parallel ----
    {
        const float* xrow = x + b * INSZ;
        float* orow = out + b * OUTSZ;
        int idr = sids[(w << 5) + l];
        if (idr >= 0) {
            float contrib = e[0] * xrow[idr & 1023];
            atomicAdd(&orow[(idr >> 10) & 1023], contrib);
        }
    }
}

extern "C" void kernel_launch(void* const* d_in, const int* in_sizes, int n_in,
                              void* d_out, int out_size)
{
    const float* x      = (const float*)d_in[0];
    const float* means  = (const float*)d_in[1];
    const float* sigmas = (const float*)d_in[2];
    const float* values = (const float*)d_in[3];
    const float* su     = (const float*)d_in[4];
    const float* ru     = (const float*)d_in[5];
    float* out = (float*)d_out;

    cudaMemsetAsync(out, 0, (size_t)out_size * sizeof(float));
    sparse_layer_kernel<<<BB * KK, NP>>>(x, means, sigmas, values, su, ru, out);
}

// round 5
// speedup vs baseline: 3.3399x; 1.2073x over previous
#include <cuda_runtime.h>
#include <math.h>

// Fixed problem shapes: b=8, n=4096, c=32, g=4, rad=4, rank=2, k=128, in=1024, OUT=1024
#define BB    8
#define CC    32
#define GG    4
#define RADR  4
#define KK    128
#define PPC   12          // 4 neighbor + 4 sampled + 4 range-restricted
#define NP    384         // CC * PPC points per (b,k) tile
#define INSZ  1024
#define OUTSZ 1024
#define NWARP 12          // NP/32
#define HSZ   1024        // dup-hash slots (power of 2)

// sqrt(0.5 * log2(e)) — folds the -0.5 and the exp->exp2 conversion into the
// per-cell inverse sigmas, so the inner loop needs no scale multiply at all.
#define SQRT_HALF_LOG2E 0.8493218383f

__device__ __forceinline__ float ex2_approx(float v) {
    float r;
    asm("ex2.approx.f32 %0, %1;" : "=f"(r) : "f"(v));
    return r;
}

__global__ __launch_bounds__(NP) void sparse_layer_kernel(
    const float* __restrict__ x,        // (8, 1024)
    const float* __restrict__ means,    // (8, 4096, 2)
    const float* __restrict__ sigmas,   // (8, 4096, 2)
    const float* __restrict__ values,   // (8, 4096)
    const float* __restrict__ su,       // (8, 128, 32, 4, 2)
    const float* __restrict__ ru,       // (8, 128, 32, 4, 2)
    float* __restrict__ out)            // (8, 1024)
{
    __shared__ float sm0[CC], sm1[CC], si0[CC], si1[CC], sval[CC];
    __shared__ int    sids[NP];             // bit31 = dup, low 20 bits = i0*1024+i1
    __shared__ float2 spts[NP];             // (p0 as float, or 1e30 if dup; p1)
    __shared__ float spart[NWARP * CC];
    __shared__ float svalw[CC];
    __shared__ unsigned int tab[HSZ];       // hash: (id<<9)|minidx, EMPTY=0xFFFFFFFF

    const int bk = blockIdx.x;              // b*128 + k
    const int b  = bk >> 7;
    const int t  = threadIdx.x;
    const int w  = t >> 5;
    const int l  = t & 31;

    // ---- init hash + load per-cell params ----
    #pragma unroll
    for (int i = t; i < HSZ; i += NP) tab[i] = 0xFFFFFFFFu;
    if (t < CC) {
        int base = (bk * CC + t) * 2;
        sm0[t] = means[base];
        sm1[t] = means[base + 1];
        si0[t] = sqrtf(1.0f / (1e-6f + sigmas[base]))     * SQRT_HALF_LOG2E;
        si1[t] = sqrtf(1.0f / (1e-6f + sigmas[base + 1])) * SQRT_HALF_LOG2E;
        sval[t] = values[bk * CC + t];
    }
    __syncthreads();

    // ---- generate integer tuple for this thread's point: cell c = t/12, slot j ----
    int id;
    {
        const int c = t / PPC;
        const int j = t - c * PPC;
        const float m0v = sm0[c], m1v = sm1[c];
        const float SCL = 1.0f - 1e-6f;
        int i0, i1;
        if (j < 4) {
            // fm order (itertools.product([T,F],2)): True->floor
            i0 = (j & 2) ? (int)ceilf(m0v) : (int)floorf(m0v);
            i1 = (j & 1) ? (int)ceilf(m1v) : (int)floorf(m1v);
        } else if (j < 8) {
            int idx = ((bk * CC + c) * GG + (j - 4)) * 2;
            i0 = (int)floorf(__fmul_rn(__fmul_rn(su[idx],     SCL), 1024.0f));
            i1 = (int)floorf(__fmul_rn(__fmul_rn(su[idx + 1], SCL), 1024.0f));
        } else {
            int idx = ((bk * CC + c) * RADR + (j - 8)) * 2;
            float mn0 = rintf(m0v), mn1 = rintf(m1v);   // round half-even (jnp.round)
            float lo0 = mn0 - 8.0f, lo1 = mn1 - 8.0f;
            if (lo0 < 0.0f) lo0 = 0.0f;
            if (mn0 + 8.0f > 1024.0f) lo0 = 1008.0f;
            if (lo1 < 0.0f) lo1 = 0.0f;
            if (mn1 + 8.0f > 1024.0f) lo1 = 1008.0f;
            i0 = (int)floorf(__fadd_rn(__fmul_rn(__fmul_rn(ru[idx],     SCL), 16.0f), lo0));
            i1 = (int)floorf(__fadd_rn(__fmul_rn(__fmul_rn(ru[idx + 1], SCL), 16.0f), lo1));
        }
        id = (i0 << 10) | i1;
    }

    // ---- duplicate marking via shared hash (first occurrence by thread index wins) ----
    {
        const unsigned int uid = (unsigned int)id;
        const unsigned int val = (uid << 9) | (unsigned int)t;   // 20+9 bits < 2^29
        unsigned int h = (uid * 2654435761u) >> 22;              // top 10 bits
        int slot;
        for (;;) {
            unsigned int old = atomicCAS(&tab[h], 0xFFFFFFFFu, val);
            if (old == 0xFFFFFFFFu) { slot = h; break; }         // claimed slot
            if ((old >> 9) == uid)  { atomicMin(&tab[h], val); slot = h; break; }
            h = (h + 1) & (HSZ - 1);
        }
        __syncthreads();
        bool dup = ((tab[slot] & 511u) != (unsigned int)t);
        sids[t] = dup ? (id | (int)0x80000000) : id;
        // dup -> p0 = 1e30 => exponent underflows to -inf => ex2 gives exact 0
        spts[t] = make_float2(dup ? 1e30f : (float)(id >> 10), (float)(id & 1023));
    }
    __syncthreads();

    // ---- density pass: warp w owns points [32w,32w+32), lane = cell ----
    const float v0 = si0[l], v1 = si1[l];
    const float m0v0 = sm0[l] * v0, m1v1 = sm1[l] * v1;
    float e[32];
    float colp = 0.0f;
    #pragma unroll
    for (int ii = 0; ii < 32; ++ii) {
        float2 p = spts[(w << 5) + ii];             // LDS.64 broadcast
        float d0 = __fmaf_rn(p.x, v0, -m0v0);
        float d1 = __fmaf_rn(p.y, v1, -m1v1);
        float s  = __fmaf_rn(-d1, d1, __fmul_rn(-d0, d0));  // s = -(d0^2+d1^2), negs free
        float ee = ex2_approx(s);
        e[ii] = ee;
        colp += ee;
    }
    spart[w * CC + l] = colp;
    __syncthreads();

    // ---- column sums and value/colsum weights ----
    if (t < CC) {
        float s = 0.0f;
        #pragma unroll
        for (int ww = 0; ww < NWARP; ++ww) s += spart[ww * CC + t];
        svalw[t] = sval[t] / s;
    }
    __syncthreads();

    // ---- per-point weighted sums via 32x32 register transpose-reduce ----
    {
        const float vwl = svalw[l];
        #pragma unroll
        for (int ii = 0; ii < 32; ++ii) e[ii] *= vwl;

        #pragma unroll
        for (int mask = 16; mask >= 1; mask >>= 1) {
            const bool hi = (l & mask) != 0;
            #pragma unroll
            for (int j = 0; j < mask; ++j) {
                float a = e[j], bq = e[j + mask];
                float keep = hi ? bq : a;
                float give = hi ? a : bq;
                e[j] = keep + __shfl_xor_sync(0xffffffffu, give, mask);
            }
        }
    }

    // ---- scatter: one atomic per live point, 32 lanes in parallel ----
    {
        const float* xrow = x + b * INSZ;
        float* orow = out + b * OUTSZ;
        int idr = sids[(w << 5) + l];
        if (idr >= 0) {
            float contrib = e[0] * xrow[idr & 1023];
            atomicAdd(&orow[(idr >> 10) & 1023], contrib);
        }
    }
}

extern "C" void kernel_launch(void* const* d_in, const int* in_sizes, int n_in,
                              void* d_out, int out_size)
{
    const float* x      = (const float*)d_in[0];
    const float* means  = (const float*)d_in[1];
    const float* sigmas = (const float*)d_in[2];
    const float* values = (const float*)d_in[3];
    const float* su     = (const float*)d_in[4];
    const float* ru     = (const float*)d_in[5];
    float* out = (float*)d_out;

    cudaMemsetAsync(out, 0, (size_t)out_size * sizeof(float));
    sparse_layer_kernel<<<BB * KK, NP>>>(x, means, sigmas, values, su, ru, out);
}